// round 1
// baseline (speedup 1.0000x reference)
#include <cuda_runtime.h>

// Inputs (metadata order):
// 0: user_id  int32 [16384]
// 1: item_id  int32 [16384]
// 2: category int32 [16384]
// 3: emb_user f32 [100000]
// 4: emb_item f32 [50000]
// 5: emb_cat  f32 [1000]
// 6: cross_w  f32 [150000000]
// out: f32 [16384]

#define D_CAT 1000LL
#define OFF_IC 100000000LL  // D_USER * D_CAT

__global__ void wide_kernel(const int* __restrict__ user_id,
                            const int* __restrict__ item_id,
                            const int* __restrict__ category,
                            const float* __restrict__ emb_user,
                            const float* __restrict__ emb_item,
                            const float* __restrict__ emb_cat,
                            const float* __restrict__ cross_w,
                            float* __restrict__ out,
                            int n) {
    int i = blockIdx.x * blockDim.x + threadIdx.x;
    if (i >= n) return;
    long long u = user_id[i];
    long long it = item_id[i];
    long long c = category[i];
    // 5 independent gathers — MLP=5, latency overlapped across 512 warps
    float a = __ldg(&emb_user[u]);
    float b = __ldg(&emb_item[it]);
    float d = __ldg(&emb_cat[c]);
    float e = __ldg(&cross_w[u * D_CAT + c]);
    float f = __ldg(&cross_w[OFF_IC + it * D_CAT + c]);
    out[i] = a + b + d + e + f;
}

extern "C" void kernel_launch(void* const* d_in, const int* in_sizes, int n_in,
                              void* d_out, int out_size) {
    const int* user_id  = (const int*)d_in[0];
    const int* item_id  = (const int*)d_in[1];
    const int* category = (const int*)d_in[2];
    const float* emb_user = (const float*)d_in[3];
    const float* emb_item = (const float*)d_in[4];
    const float* emb_cat  = (const float*)d_in[5];
    const float* cross_w  = (const float*)d_in[6];
    float* out = (float*)d_out;
    int n = in_sizes[0];
    int threads = 256;
    int blocks = (n + threads - 1) / threads;
    wide_kernel<<<blocks, threads>>>(user_id, item_id, category,
                                     emb_user, emb_item, emb_cat, cross_w,
                                     out, n);
}

// round 2
// speedup vs baseline: 1.0048x; 1.0048x over previous
#include <cuda_runtime.h>

// Inputs (metadata order):
// 0: user_id  int32 [16384]
// 1: item_id  int32 [16384]
// 2: category int32 [16384]
// 3: emb_user f32 [100000]
// 4: emb_item f32 [50000]
// 5: emb_cat  f32 [1000]
// 6: cross_w  f32 [150000000]
// out: f32 [16384]
//
// out[i] = emb_user[u] + emb_item[it] + emb_cat[c]
//        + cross_w[u*1000 + c] + cross_w[1e8 + it*1000 + c]
//
// Latency-bound micro-kernel: 5 independent gathers per thread (MLP=5),
// hot cross_w sectors (~1MB) are L2-resident across graph replays.
// Layout: 128 blocks x 128 threads = 1 CTA on each of 128 SMs (single
// wave), minimizing per-SM L1tex queue depth.

#define D_CAT 1000
#define OFF_IC 100000000

__global__ void __launch_bounds__(128, 1)
wide_kernel(const int* __restrict__ user_id,
            const int* __restrict__ item_id,
            const int* __restrict__ category,
            const float* __restrict__ emb_user,
            const float* __restrict__ emb_item,
            const float* __restrict__ emb_cat,
            const float* __restrict__ cross_w,
            float* __restrict__ out,
            int n) {
    int i = blockIdx.x * 128 + threadIdx.x;
    if (i >= n) return;
    // 3 coalesced index loads
    int u  = user_id[i];
    int it = item_id[i];
    int c  = category[i];
    // int32 index math (max idx ~1.5e8 < 2^31); sign-extend at address
    int idx_uc = u * D_CAT + c;
    int idx_ic = OFF_IC + it * D_CAT + c;
    // 5 independent gathers — issued back-to-back, latency overlapped
    float a = __ldg(&emb_user[u]);
    float b = __ldg(&emb_item[it]);
    float d = __ldg(&emb_cat[c]);
    float e = __ldg(&cross_w[idx_uc]);
    float f = __ldg(&cross_w[idx_ic]);
    out[i] = (a + b) + (d + e) + f;
}

extern "C" void kernel_launch(void* const* d_in, const int* in_sizes, int n_in,
                              void* d_out, int out_size) {
    const int* user_id  = (const int*)d_in[0];
    const int* item_id  = (const int*)d_in[1];
    const int* category = (const int*)d_in[2];
    const float* emb_user = (const float*)d_in[3];
    const float* emb_item = (const float*)d_in[4];
    const float* emb_cat  = (const float*)d_in[5];
    const float* cross_w  = (const float*)d_in[6];
    float* out = (float*)d_out;
    int n = in_sizes[0];
    int threads = 128;
    int blocks = (n + threads - 1) / threads;  // 128 blocks for n=16384
    wide_kernel<<<blocks, threads>>>(user_id, item_id, category,
                                     emb_user, emb_item, emb_cat, cross_w,
                                     out, n);
}